// round 9
// baseline (speedup 1.0000x reference)
#include <cuda_runtime.h>
#include <math.h>
#include <stdint.h>

// Problem constants
#define BB 4
#define TT 10
#define SS 6
#define AA 6
#define HID 512
#define LL 6
#define IMGD 128
#define NPIX 16384          // 128*128
#define NIMG_CAM 40         // B*T per camera
#define NIMG 80

// fp32 (layer-1) patch layout
#define PROW 36
#define PCH  (34 * PROW)

// tf32 pair-interleaved patch layout
#define PROW2 72            // 36 cols * 2 (ci pair)
#define PCQ   2472          // padded: 34*72=2448 -> 2472 (stride % 32 == 8)
#define WCQ   296           // padded: 9*16*2=288 -> 296 (stride % 32 == 8)
#define PATCH_FLOATS (4 * PCQ)   // 9888 per buffer
#define WS_FLOATS    (4 * WCQ)   // 1184 per buffer

// ---------------------------------------------------------------------------
// Scratch (static __device__ globals: allocation-free per harness rules)
// ---------------------------------------------------------------------------
__device__ float g_bufA[(size_t)NIMG * 128 * NPIX];   // max 128 ch
__device__ float g_bufB[(size_t)NIMG * 64 * NPIX];    // max 64 ch
__device__ float g_feat[NIMG_CAM * 64];               // (b*T+t, 64)
__device__ float g_h[2 * LL * BB * HID];              // double-buffered h
__device__ float g_c[LL * BB * HID];

// ---------------------------------------------------------------------------
// f32x2 packed-FMA helpers (layer-1 fp32 conv)
// ---------------------------------------------------------------------------
__device__ __forceinline__ unsigned long long pack2(float a, float b) {
    unsigned long long r;
    asm("mov.b64 %0, {%1, %2};" : "=l"(r) : "r"(__float_as_uint(a)), "r"(__float_as_uint(b)));
    return r;
}
__device__ __forceinline__ void unpack2(unsigned long long v, float& a, float& b) {
    unsigned int lo, hi;
    asm("mov.b64 {%0, %1}, %2;" : "=r"(lo), "=r"(hi) : "l"(v));
    a = __uint_as_float(lo); b = __uint_as_float(hi);
}
__device__ __forceinline__ void fma2(unsigned long long& d, unsigned long long a, unsigned long long b) {
    asm("fma.rn.f32x2 %0, %1, %2, %0;" : "+l"(d) : "l"(a), "l"(b));
}

// ---------------------------------------------------------------------------
// cp.async helpers
// ---------------------------------------------------------------------------
__device__ __forceinline__ void cp_async4(uint32_t smem_addr, const void* gptr, int sz) {
    asm volatile("cp.async.ca.shared.global [%0], [%1], 4, %2;\n"
                 :: "r"(smem_addr), "l"(gptr), "r"(sz));
}
__device__ __forceinline__ void cp_commit() { asm volatile("cp.async.commit_group;"); }
template<int N>
__device__ __forceinline__ void cp_wait() { asm volatile("cp.async.wait_group %0;" :: "n"(N)); }

// ---------------------------------------------------------------------------
// tf32 mma m16n8k8 (row.col), fp32 accumulate
// ---------------------------------------------------------------------------
__device__ __forceinline__ void mma_tf32(float* d, const float* a, const float* b) {
    asm volatile(
        "mma.sync.aligned.m16n8k8.row.col.f32.tf32.tf32.f32 "
        "{%0,%1,%2,%3}, {%4,%5,%6,%7}, {%8,%9}, {%0,%1,%2,%3};"
        : "+f"(d[0]), "+f"(d[1]), "+f"(d[2]), "+f"(d[3])
        : "r"(__float_as_uint(a[0])), "r"(__float_as_uint(a[1])),
          "r"(__float_as_uint(a[2])), "r"(__float_as_uint(a[3])),
          "r"(__float_as_uint(b[0])), "r"(__float_as_uint(b[1])));
}

// ---------------------------------------------------------------------------
// Staging for the tf32 kernel: pair-interleaved layouts.
// ws:    [cq][k][ko][hi]   (WCQ stride per cq)
// patch: [cq][py][px][hi]  (PCQ stride per cq, PROW2 per row)
// ---------------------------------------------------------------------------
template<int CIN>
__device__ __forceinline__ void stage_chunk_tf32(
    const float* __restrict__ ib, const float* __restrict__ wt,
    int g, int bx, int by, int c0,
    uint32_t ws_s, uint32_t patch_s, int tid)
{
    constexpr int CB = 8;
    for (int idx = tid; idx < CB * 144; idx += 256) {
        int ci = idx / 144;
        int rem = idx - ci * 144;
        int k = rem >> 4;
        int ko = rem & 15;
        const float* src = wt + ((size_t)(g * 16 + ko) * CIN + (c0 + ci)) * 9 + k;
        uint32_t dst = ws_s + (uint32_t)(((ci & 3) * WCQ + k * 32 + ko * 2 + (ci >> 2)) * 4);
        cp_async4(dst, src, 4);
    }
    for (int idx = tid; idx < CB * 1156; idx += 256) {
        int ci = idx / 1156;
        int rem = idx - ci * 1156;
        int py = rem / 34;
        int px = rem - py * 34;
        int gy = by * 32 + py - 1;
        int gx = bx * 32 + px - 1;
        bool ok = ((unsigned)gy < 128u) && ((unsigned)gx < 128u);
        const float* src = ib + (size_t)(c0 + ci) * NPIX + (ok ? (gy * IMGD + gx) : 0);
        uint32_t dst = patch_s + (uint32_t)(((ci & 3) * PCQ + py * PROW2 + px * 2 + (ci >> 2)) * 4);
        cp_async4(dst, src, ok ? 4 : 0);
    }
}

// ---------------------------------------------------------------------------
// tf32 tensor-core 3x3 SAME conv + bias + relu.  Dual-camera (img<40 -> cam0).
// Block: 32x32 pixel tile x 16 ko, 256 threads (8 warps).
// Warp: 8-row band x 16 x-pixels x 16 ko; A/B fragments fetched as LDS.64
// pairs (ci, ci+4 interleaved), conflict-free banks.
// ---------------------------------------------------------------------------
template<int CIN>
__global__ void __launch_bounds__(256, 2) conv3x3_tf32_kernel(
    const float* __restrict__ in,
    const float* __restrict__ wt0, const float* __restrict__ wt1,
    const float* __restrict__ bias0, const float* __restrict__ bias1,
    float* __restrict__ out, int groups)
{
    constexpr int CB = 8;
    constexpr int NCHUNK = CIN / CB;

    extern __shared__ __align__(16) float smem[];
    float* ws_base = smem;                         // 2 * WS_FLOATS
    float* patch_base = smem + 2 * WS_FLOATS;      // 2 * PATCH_FLOATS
    uint32_t sbase = (uint32_t)__cvta_generic_to_shared(smem);
    const uint32_t ws_off[2] = { sbase, sbase + (uint32_t)(WS_FLOATS * 4) };
    const uint32_t pa_off[2] = { sbase + (uint32_t)(2 * WS_FLOATS * 4),
                                 sbase + (uint32_t)((2 * WS_FLOATS + PATCH_FLOATS) * 4) };

    const int img = blockIdx.z / groups;
    const int grp = blockIdx.z % groups;
    const float* wt   = (img < NIMG_CAM) ? wt0 : wt1;
    const float* bias = (img < NIMG_CAM) ? bias0 : bias1;

    const int tid = threadIdx.x;
    const int w    = tid >> 5;
    const int lane = tid & 31;
    const int lg   = lane >> 2;         // 0..7
    const int tig  = lane & 3;          // 0..3
    const int wy   = w >> 1;            // band 0..3
    const int x0   = (w & 1) * 16;
    const int bx = (int)blockIdx.x;
    const int by = (int)blockIdx.y;

    const float* ib = in + (size_t)img * CIN * NPIX;

    float d[8][2][4];
#pragma unroll
    for (int sb = 0; sb < 8; sb++)
#pragma unroll
        for (int h = 0; h < 2; h++)
#pragma unroll
            for (int i = 0; i < 4; i++) d[sb][h][i] = 0.f;

    stage_chunk_tf32<CIN>(ib, wt, grp, bx, by, 0, ws_off[0], pa_off[0], tid);
    cp_commit();
    if (NCHUNK > 1) {
        stage_chunk_tf32<CIN>(ib, wt, grp, bx, by, CB, ws_off[1], pa_off[1], tid);
        cp_commit();
    }

    for (int ch = 0; ch < NCHUNK; ch++) {
        const int cur = ch & 1;
        if (ch + 1 < NCHUNK) cp_wait<1>(); else cp_wait<0>();
        __syncthreads();

        const float* WB = ws_base + cur * WS_FLOATS + tig * WCQ + lg * 2;
        const float* PA = patch_base + cur * PATCH_FLOATS
                        + tig * PCQ + (wy * 8) * PROW2 + (x0 + lg) * 2;

#pragma unroll
        for (int kx = 0; kx < 3; kx++) {
            // 10 rows of A fragments: two LDS.64 each (x and x+8, ci pair)
            float a[10][4];
#pragma unroll
            for (int r = 0; r < 10; r++) {
                float2 fa = *(const float2*)(PA + r * PROW2 + kx * 2);
                float2 fb = *(const float2*)(PA + r * PROW2 + kx * 2 + 16);
                a[r][0] = fa.x; a[r][1] = fb.x; a[r][2] = fa.y; a[r][3] = fb.y;
            }
#pragma unroll
            for (int ky = 0; ky < 3; ky++) {
                const int k = ky * 3 + kx;
                float2 B0 = *(const float2*)(WB + k * 32);        // ko = lg
                float2 B1 = *(const float2*)(WB + k * 32 + 16);   // ko = lg + 8
                float b0[2] = { B0.x, B0.y };
                float b1[2] = { B1.x, B1.y };
#pragma unroll
                for (int sb = 0; sb < 8; sb++) {
                    mma_tf32(d[sb][0], a[sb + ky], b0);
                    mma_tf32(d[sb][1], a[sb + ky], b1);
                }
            }
        }

        if (ch + 2 < NCHUNK) {
            __syncthreads();
            stage_chunk_tf32<CIN>(ib, wt, grp, bx, by, (ch + 2) * CB,
                                  ws_off[cur], pa_off[cur], tid);
            cp_commit();
        }
    }

    // epilogue: bias + relu + scalar stores
    float* ob = out + ((size_t)img * (groups * 16) + grp * 16) * NPIX;
    const int gxa = bx * 32 + x0 + lg;
    const int gxb = gxa + 8;
#pragma unroll
    for (int h = 0; h < 2; h++) {
        const int ko0 = h * 8 + 2 * tig;
        const float bi0 = bias[grp * 16 + ko0];
        const float bi1 = bias[grp * 16 + ko0 + 1];
        float* o0 = ob + (size_t)ko0 * NPIX;
        float* o1 = ob + (size_t)(ko0 + 1) * NPIX;
#pragma unroll
        for (int sb = 0; sb < 8; sb++) {
            const int gy = by * 32 + wy * 8 + sb;
            o0[gy * IMGD + gxa] = fmaxf(d[sb][h][0] + bi0, 0.f);
            o1[gy * IMGD + gxa] = fmaxf(d[sb][h][1] + bi1, 0.f);
            o0[gy * IMGD + gxb] = fmaxf(d[sb][h][2] + bi0, 0.f);
            o1[gy * IMGD + gxb] = fmaxf(d[sb][h][3] + bi1, 0.f);
        }
    }
}

// ---------------------------------------------------------------------------
// Layer-1 fp32 conv staging (scalar layout)
// ---------------------------------------------------------------------------
template<int CIN, int CB>
__device__ __forceinline__ void stage_chunk_f32(
    const float* __restrict__ ib, const float* __restrict__ wt,
    int g, int bx, int by, int c0,
    uint32_t ws_s, uint32_t patch_s, int tid)
{
    for (int idx = tid; idx < CB * 144; idx += 256) {
        int ci = idx / 144;
        int rem = idx - ci * 144;
        int k = rem >> 4;
        int ko = rem & 15;
        const float* src = wt + ((size_t)(g * 16 + ko) * CIN + (c0 + ci)) * 9 + k;
        cp_async4(ws_s + idx * 4, src, 4);
    }
    for (int idx = tid; idx < CB * 1156; idx += 256) {
        int ci = idx / 1156;
        int rem = idx - ci * 1156;
        int py = rem / 34;
        int px = rem - py * 34;
        int gy = by * 32 + py - 1;
        int gx = bx * 32 + px - 1;
        bool ok = ((unsigned)gy < 128u) && ((unsigned)gx < 128u);
        const float* src = ib + (size_t)ci * NPIX + (ok ? (gy * IMGD + gx) : 0);
        cp_async4(patch_s + (ci * PCH + py * PROW + px) * 4, src, ok ? 4 : 0);
    }
}

// ---------------------------------------------------------------------------
// Layer-1 fp32 conv (CIN=3), dual-camera.
// ---------------------------------------------------------------------------
__global__ void __launch_bounds__(256, 2) conv3x3_l1_kernel(
    const float* __restrict__ in0, const float* __restrict__ in1,
    const float* __restrict__ wt0, const float* __restrict__ wt1,
    const float* __restrict__ bias0, const float* __restrict__ bias1,
    float* __restrict__ out, int groups)
{
    constexpr int CIN = 3;
    constexpr int CB = 3;

    extern __shared__ __align__(16) float smem[];
    float* ws_base = smem;
    float* patch_base = smem + CB * 144;
    uint32_t sbase = (uint32_t)__cvta_generic_to_shared(smem);
    const uint32_t ws_s = sbase;
    const uint32_t pa_s = sbase + (uint32_t)(CB * 144 * 4);

    const int img = blockIdx.z / groups;
    const int g   = blockIdx.z % groups;
    const float* wt   = (img < NIMG_CAM) ? wt0 : wt1;
    const float* bias = (img < NIMG_CAM) ? bias0 : bias1;
    const int limg = (img < NIMG_CAM) ? img : (img - NIMG_CAM);
    const float* ib = ((img < NIMG_CAM) ? in0 : in1) + (size_t)limg * CIN * NPIX;

    const int tid = threadIdx.x;
    const int tx  = tid & 15;
    const int ty  = tid >> 4;
    const int bx  = (int)blockIdx.x;
    const int by  = (int)blockIdx.y;
    const int ox0 = bx * 32 + 2 * tx;
    const int oy0 = by * 32 + 2 * ty;

    unsigned long long acc[4][8];
    const unsigned long long z2 = pack2(0.f, 0.f);
#pragma unroll
    for (int p_ = 0; p_ < 4; p_++)
#pragma unroll
        for (int i = 0; i < 8; i++) acc[p_][i] = z2;

    stage_chunk_f32<CIN, CB>(ib, wt, g, bx, by, 0, ws_s, pa_s, tid);
    cp_commit();
    cp_wait<0>();
    __syncthreads();

#pragma unroll
    for (int ci = 0; ci < CB; ci++) {
        float p[4][4];
        const float* pb = patch_base + ci * PCH + (2 * ty) * PROW + 2 * tx;
#pragma unroll
        for (int r = 0; r < 4; r++) {
            float2 a = *(const float2*)(pb + r * PROW);
            float2 b = *(const float2*)(pb + r * PROW + 2);
            p[r][0] = a.x; p[r][1] = a.y; p[r][2] = b.x; p[r][3] = b.y;
        }
        const float* wk = ws_base + ci * 144;
#pragma unroll
        for (int k = 0; k < 9; k++) {
            const int ky = k / 3, kx = k - 3 * (k / 3);
            const ulonglong2* wp = (const ulonglong2*)(wk + k * 16);
            ulonglong2 w01 = wp[0];
            ulonglong2 w23 = wp[1];
            ulonglong2 w45 = wp[2];
            ulonglong2 w67 = wp[3];
#pragma unroll
            for (int p_ = 0; p_ < 4; p_++) {
                float v = p[(p_ >> 1) + ky][(p_ & 1) + kx];
                unsigned long long bb = pack2(v, v);
                fma2(acc[p_][0], w01.x, bb);
                fma2(acc[p_][1], w01.y, bb);
                fma2(acc[p_][2], w23.x, bb);
                fma2(acc[p_][3], w23.y, bb);
                fma2(acc[p_][4], w45.x, bb);
                fma2(acc[p_][5], w45.y, bb);
                fma2(acc[p_][6], w67.x, bb);
                fma2(acc[p_][7], w67.y, bb);
            }
        }
    }

    float* ob = out + ((size_t)img * (groups * 16) + g * 16) * NPIX;
#pragma unroll
    for (int i = 0; i < 8; i++) {
        float b0 = bias[g * 16 + 2 * i];
        float b1 = bias[g * 16 + 2 * i + 1];
#pragma unroll
        for (int pr = 0; pr < 2; pr++) {
            float a0l, a1l, a0r, a1r;
            unpack2(acc[pr * 2 + 0][i], a0l, a1l);
            unpack2(acc[pr * 2 + 1][i], a0r, a1r);
            int row = oy0 + pr;
            float2 v0 = make_float2(fmaxf(a0l + b0, 0.f), fmaxf(a0r + b0, 0.f));
            float2 v1 = make_float2(fmaxf(a1l + b1, 0.f), fmaxf(a1r + b1, 0.f));
            *(float2*)(ob + (size_t)(2 * i) * NPIX + row * IMGD + ox0) = v0;
            *(float2*)(ob + (size_t)(2 * i + 1) * NPIX + row * IMGD + ox0) = v1;
        }
    }
}

// ---------------------------------------------------------------------------
// Spatial softmax
// ---------------------------------------------------------------------------
__global__ void __launch_bounds__(256) sspmax_kernel(
    const float* __restrict__ conv16, float* __restrict__ feat)
{
    __shared__ float red[8];
    __shared__ float r2[3][8];

    const int id = blockIdx.x;
    const int img = id >> 4;
    const int ch = id & 15;
    const int cam = (img >= NIMG_CAM) ? 1 : 0;
    const int bt = img - cam * NIMG_CAM;
    const float* p = conv16 + ((size_t)img * 16 + ch) * NPIX;
    const int tid = threadIdx.x;

    float m = -1e30f;
    for (int k = tid; k < NPIX; k += 256) m = fmaxf(m, p[k]);
    for (int o = 16; o; o >>= 1) m = fmaxf(m, __shfl_xor_sync(~0u, m, o));
    if ((tid & 31) == 0) red[tid >> 5] = m;
    __syncthreads();
    if (tid < 8) {
        float v = red[tid];
        for (int o = 4; o; o >>= 1) v = fmaxf(v, __shfl_xor_sync(0xffu, v, o));
        if (tid == 0) red[0] = v;
    }
    __syncthreads();
    m = red[0];

    float se = 0.f, sx = 0.f, sy = 0.f;
    const float step = 2.f / 127.f;
    for (int k = tid; k < NPIX; k += 256) {
        float e = expf(p[k] - m);
        float px = -1.f + (float)(k & 127) * step;
        float py = -1.f + (float)(k >> 7) * step;
        se += e; sx += e * px; sy += e * py;
    }
    for (int o = 16; o; o >>= 1) {
        se += __shfl_xor_sync(~0u, se, o);
        sx += __shfl_xor_sync(~0u, sx, o);
        sy += __shfl_xor_sync(~0u, sy, o);
    }
    if ((tid & 31) == 0) { r2[0][tid >> 5] = se; r2[1][tid >> 5] = sx; r2[2][tid >> 5] = sy; }
    __syncthreads();
    if (tid == 0) {
        float a = 0.f, bx = 0.f, by = 0.f;
        for (int w = 0; w < 8; w++) { a += r2[0][w]; bx += r2[1][w]; by += r2[2][w]; }
        feat[bt * 64 + cam * 32 + 2 * ch + 0] = bx / a;
        feat[bt * 64 + cam * 32 + 2 * ch + 1] = by / a;
    }
}

// ---------------------------------------------------------------------------
// LSTM cell
// ---------------------------------------------------------------------------
__device__ __forceinline__ float sigm(float x) { return 1.f / (1.f + expf(-x)); }

__global__ void __launch_bounds__(256) lstm_cell_kernel(
    const float* __restrict__ xa, int alen, int xa_stride,
    const float* __restrict__ im,
    const float* __restrict__ wih, const float* __restrict__ whh,
    const float* __restrict__ bih, const float* __restrict__ bhh,
    const float* __restrict__ hprev, float* __restrict__ hnew,
    float* __restrict__ c)
{
    __shared__ float xs[BB][576];
    __shared__ float hs[BB][HID];
    __shared__ float part[8][BB];
    __shared__ float gs[16];

    const int inlen = alen + 64;
    const int tid = threadIdx.x;

    for (int idx = tid; idx < BB * inlen; idx += 256) {
        int b = idx / inlen;
        int k = idx - b * inlen;
        xs[b][k] = (k < alen) ? xa[b * xa_stride + k] : im[b * (TT * 64) + (k - alen)];
    }
    for (int idx = tid; idx < BB * HID; idx += 256)
        hs[idx >> 9][idx & 511] = hprev[idx];
    __syncthreads();

    const int j = blockIdx.x;
    const int warp = tid >> 5;
    const int lane = tid & 31;
    const int g = warp >> 1;
    const int half = warp & 1;
    const int row = g * HID + j;
    const int k0 = half * 32 + lane;

    float s0 = 0.f, s1 = 0.f, s2 = 0.f, s3 = 0.f;
    const float* wr = wih + (size_t)row * inlen;
#pragma unroll 4
    for (int k = k0; k < inlen; k += 64) {
        float w = wr[k];
        s0 += w * xs[0][k]; s1 += w * xs[1][k];
        s2 += w * xs[2][k]; s3 += w * xs[3][k];
    }
    const float* hr = whh + (size_t)row * HID;
#pragma unroll 4
    for (int k = k0; k < HID; k += 64) {
        float w = hr[k];
        s0 += w * hs[0][k]; s1 += w * hs[1][k];
        s2 += w * hs[2][k]; s3 += w * hs[3][k];
    }
    for (int o = 16; o; o >>= 1) {
        s0 += __shfl_xor_sync(~0u, s0, o);
        s1 += __shfl_xor_sync(~0u, s1, o);
        s2 += __shfl_xor_sync(~0u, s2, o);
        s3 += __shfl_xor_sync(~0u, s3, o);
    }
    if (lane == 0) {
        part[warp][0] = s0; part[warp][1] = s1;
        part[warp][2] = s2; part[warp][3] = s3;
    }
    __syncthreads();

    if (tid < 16) {
        int gg = tid >> 2, b = tid & 3;
        float s = part[gg * 2][b] + part[gg * 2 + 1][b]
                + bih[gg * HID + j] + bhh[gg * HID + j];
        gs[b * 4 + gg] = s;
    }
    __syncthreads();

    if (tid < BB) {
        const int b = tid;
        float gi = gs[b * 4 + 0];
        float gf = gs[b * 4 + 1];
        float gg = gs[b * 4 + 2];
        float go = gs[b * 4 + 3];
        float cold = c[b * HID + j];
        float cn = sigm(gf) * cold + sigm(gi) * tanhf(gg);
        float hn = sigm(go) * tanhf(cn);
        c[b * HID + j] = cn;
        hnew[b * HID + j] = hn;
    }
}

// ---------------------------------------------------------------------------
// Output head
// ---------------------------------------------------------------------------
__global__ void __launch_bounds__(128) out_kernel(
    const float* __restrict__ h, const float* __restrict__ im,
    const float* __restrict__ ow, const float* __restrict__ ob,
    float* __restrict__ outp)
{
    const int b = blockIdx.x / AA;
    const int a = blockIdx.x % AA;
    const float* w = ow + a * (HID + 64);
    float s = 0.f;
    for (int k = threadIdx.x; k < HID; k += 128) s += w[k] * h[b * HID + k];
    for (int k = threadIdx.x; k < 64; k += 128) s += w[HID + k] * im[b * (TT * 64) + k];
    __shared__ float red[4];
    for (int o = 16; o; o >>= 1) s += __shfl_xor_sync(~0u, s, o);
    if ((threadIdx.x & 31) == 0) red[threadIdx.x >> 5] = s;
    __syncthreads();
    if (threadIdx.x == 0)
        outp[b * (TT * AA) + a] = red[0] + red[1] + red[2] + red[3] + ob[a];
}

__global__ void zero_state_kernel()
{
    int i = blockIdx.x * blockDim.x + threadIdx.x;
    if (i < 2 * LL * BB * HID) g_h[i] = 0.f;
    if (i < LL * BB * HID) g_c[i] = 0.f;
}

// ---------------------------------------------------------------------------
// Launch
// ---------------------------------------------------------------------------
extern "C" void kernel_launch(void* const* d_in, const int* in_sizes, int n_in,
                              void* d_out, int out_size)
{
    (void)in_sizes; (void)n_in; (void)out_size;

    const float* img_m  = (const float*)d_in[0];
    const float* img_s  = (const float*)d_in[1];
    const float* states = (const float*)d_in[2];
    const float* wih0 = (const float*)d_in[19];
    const float* whh0 = (const float*)d_in[20];
    const float* bih0 = (const float*)d_in[21];
    const float* bhh0 = (const float*)d_in[22];
    const float* wih_r = (const float*)d_in[23];
    const float* whh_r = (const float*)d_in[24];
    const float* bih_r = (const float*)d_in[25];
    const float* bhh_r = (const float*)d_in[26];
    const float* out_w = (const float*)d_in[27];
    const float* out_b = (const float*)d_in[28];
    float* outp = (float*)d_out;

    float* bufA; cudaGetSymbolAddress((void**)&bufA, g_bufA);
    float* bufB; cudaGetSymbolAddress((void**)&bufB, g_bufB);
    float* feat; cudaGetSymbolAddress((void**)&feat, g_feat);
    float* hbuf; cudaGetSymbolAddress((void**)&hbuf, g_h);
    float* cbuf; cudaGetSymbolAddress((void**)&cbuf, g_c);

    const int smemL1 = (3 * 144 + 3 * PCH) * 4;                 // 16416
    const int smemTF = 2 * (WS_FLOATS + PATCH_FLOATS) * 4;      // 88576
    cudaFuncSetAttribute(conv3x3_l1_kernel,        cudaFuncAttributeMaxDynamicSharedMemorySize, smemL1);
    cudaFuncSetAttribute(conv3x3_tf32_kernel<32>,  cudaFuncAttributeMaxDynamicSharedMemorySize, smemTF);
    cudaFuncSetAttribute(conv3x3_tf32_kernel<64>,  cudaFuncAttributeMaxDynamicSharedMemorySize, smemTF);
    cudaFuncSetAttribute(conv3x3_tf32_kernel<128>, cudaFuncAttributeMaxDynamicSharedMemorySize, smemTF);

    zero_state_kernel<<<96, 256>>>();

    // camera weights
    const float* mw[4] = { (const float*)d_in[3], (const float*)d_in[5],
                           (const float*)d_in[7], (const float*)d_in[9] };
    const float* mb[4] = { (const float*)d_in[4], (const float*)d_in[6],
                           (const float*)d_in[8], (const float*)d_in[10] };
    const float* sw[4] = { (const float*)d_in[11], (const float*)d_in[13],
                           (const float*)d_in[15], (const float*)d_in[17] };
    const float* sb[4] = { (const float*)d_in[12], (const float*)d_in[14],
                           (const float*)d_in[16], (const float*)d_in[18] };

    float* a32  = bufA;                                   // 80 imgs x 32ch
    float* b64  = bufB;                                   // 80 imgs x 64ch
    float* a128 = bufA;                                   // reuse for 128ch (after a32 consumed? NO)
    // NOTE: a32 lives in bufA[0 .. 80*32*NPIX); 128-ch output must not overlap
    // its input (b64 in bufB) nor a32 while a32 is still needed.  Layer order:
    // L1 -> a32 (bufA), L2 reads a32 -> b64 (bufB), L3 reads b64 -> a128 (bufA,
    // overwrites a32 which is dead), L4 reads a128 -> b16 (bufB offset past b64? b64 dead).
    float* b16  = bufB + (size_t)NIMG * 64 * NPIX - (size_t)NIMG * 16 * NPIX; // tail region
    // simpler: put b16 at bufB start would overwrite b64 while reading it in L4's input=a128 (bufA) — b64 IS dead by then.
    b16 = bufB;

    conv3x3_l1_kernel<<<dim3(4, 4, NIMG * 2), 256, smemL1>>>(
        img_m, img_s, mw[0], sw[0], mb[0], sb[0], a32, 2);
    conv3x3_tf32_kernel<32><<<dim3(4, 4, NIMG * 4), 256, smemTF>>>(
        a32, mw[1], sw[1], mb[1], sb[1], b64, 4);
    conv3x3_tf32_kernel<64><<<dim3(4, 4, NIMG * 8), 256, smemTF>>>(
        b64, mw[2], sw[2], mb[2], sb[2], a128, 8);
    conv3x3_tf32_kernel<128><<<dim3(4, 4, NIMG * 1), 256, smemTF>>>(
        a128, mw[3], sw[3], mb[3], sb[3], b16, 1);

    sspmax_kernel<<<NIMG * 16, 256>>>(b16, feat);

    const int half = LL * BB * HID;
    for (int t = 0; t < TT; t++) {
        float* hprev = hbuf + (t & 1) * half;
        float* hcur  = hbuf + (1 - (t & 1)) * half;
        const float* im_t = feat + t * 64;

        lstm_cell_kernel<<<HID, 256>>>(
            states + t * SS, SS, TT * SS, im_t,
            wih0, whh0, bih0, bhh0,
            hprev + 0, hcur + 0, cbuf + 0);

        for (int l = 1; l < LL; l++) {
            lstm_cell_kernel<<<HID, 256>>>(
                hcur + (size_t)(l - 1) * BB * HID, HID, HID, im_t,
                wih_r + (size_t)(l - 1) * 4 * HID * (HID + 64),
                whh_r + (size_t)(l - 1) * 4 * HID * HID,
                bih_r + (size_t)(l - 1) * 4 * HID,
                bhh_r + (size_t)(l - 1) * 4 * HID,
                hprev + (size_t)l * BB * HID,
                hcur + (size_t)l * BB * HID,
                cbuf + (size_t)l * BB * HID);
        }

        out_kernel<<<BB * AA, 128>>>(
            hcur + (size_t)(LL - 1) * BB * HID, im_t, out_w, out_b, outp + t * AA);
    }
}

// round 10
// speedup vs baseline: 1.0727x; 1.0727x over previous
#include <cuda_runtime.h>
#include <math.h>
#include <stdint.h>

// Problem constants
#define BB 4
#define TT 10
#define SS 6
#define AA 6
#define HID 512
#define LL 6
#define IMGD 128
#define NPIX 16384          // 128*128
#define NIMG_CAM 40         // B*T per camera
#define NIMG 80

// patch layout (contiguous rows, R8-style)
#define PROW 36             // padded row stride (floats)
#define PCH  (34 * PROW)    // per-channel patch floats (1224)
#define PATCH_FLOATS (8 * PCH)   // 9792 per buffer (CB=8)
#define WS_FLOATS    1152        // 9 taps * 16 ko * 8 ci

// ---------------------------------------------------------------------------
// Scratch (static __device__ globals: allocation-free per harness rules)
// ---------------------------------------------------------------------------
__device__ float g_bufA[(size_t)NIMG * 128 * NPIX];   // max 128 ch
__device__ float g_bufB[(size_t)NIMG * 64 * NPIX];    // max 64 ch
__device__ float g_feat[NIMG_CAM * 64];               // (b*T+t, 64)
__device__ float g_h[2 * LL * BB * HID];              // double-buffered h
__device__ float g_c[LL * BB * HID];

// ---------------------------------------------------------------------------
// f32x2 packed-FMA helpers (layer-1 fp32 conv)
// ---------------------------------------------------------------------------
__device__ __forceinline__ unsigned long long pack2(float a, float b) {
    unsigned long long r;
    asm("mov.b64 %0, {%1, %2};" : "=l"(r) : "r"(__float_as_uint(a)), "r"(__float_as_uint(b)));
    return r;
}
__device__ __forceinline__ void unpack2(unsigned long long v, float& a, float& b) {
    unsigned int lo, hi;
    asm("mov.b64 {%0, %1}, %2;" : "=r"(lo), "=r"(hi) : "l"(v));
    a = __uint_as_float(lo); b = __uint_as_float(hi);
}
__device__ __forceinline__ void fma2(unsigned long long& d, unsigned long long a, unsigned long long b) {
    asm("fma.rn.f32x2 %0, %1, %2, %0;" : "+l"(d) : "l"(a), "l"(b));
}

// ---------------------------------------------------------------------------
// cp.async helpers
// ---------------------------------------------------------------------------
__device__ __forceinline__ void cp_async4(uint32_t smem_addr, const void* gptr, int sz) {
    asm volatile("cp.async.ca.shared.global [%0], [%1], 4, %2;\n"
                 :: "r"(smem_addr), "l"(gptr), "r"(sz));
}
__device__ __forceinline__ void cp_commit() { asm volatile("cp.async.commit_group;"); }
template<int N>
__device__ __forceinline__ void cp_wait() { asm volatile("cp.async.wait_group %0;" :: "n"(N)); }

// ---------------------------------------------------------------------------
// tf32 mma m16n8k8 (row.col), fp32 accumulate
// ---------------------------------------------------------------------------
__device__ __forceinline__ void mma_tf32(float* d, const float* a, const float* b) {
    asm volatile(
        "mma.sync.aligned.m16n8k8.row.col.f32.tf32.tf32.f32 "
        "{%0,%1,%2,%3}, {%4,%5,%6,%7}, {%8,%9}, {%0,%1,%2,%3};"
        : "+f"(d[0]), "+f"(d[1]), "+f"(d[2]), "+f"(d[3])
        : "r"(__float_as_uint(a[0])), "r"(__float_as_uint(a[1])),
          "r"(__float_as_uint(a[2])), "r"(__float_as_uint(a[3])),
          "r"(__float_as_uint(b[0])), "r"(__float_as_uint(b[1])));
}

// ---------------------------------------------------------------------------
// tf32 staging:
//  weights -> [k][ko][cq=ci%4][hi=ci/4]   (pair-interleaved, LDS.64-friendly)
//  patch   -> [ci][py][px] contiguous rows, row-based incremental addressing
// ---------------------------------------------------------------------------
template<int CIN>
__device__ __forceinline__ void stage_chunk_tf32(
    const float* __restrict__ ib, const float* __restrict__ wt,
    int g, int bx, int by, int c0,
    uint32_t ws_s, uint32_t patch_s, int tid)
{
    constexpr int CB = 8;
    // weights: 1152 elements, div-based (few iterations)
    for (int idx = tid; idx < CB * 144; idx += 256) {
        int ci = idx / 144;
        int rem = idx - ci * 144;
        int k = rem >> 4;
        int ko = rem & 15;
        const float* src = wt + ((size_t)(g * 16 + ko) * CIN + (c0 + ci)) * 9 + k;
        uint32_t pos = (uint32_t)((((k * 16 + ko) * 4 + (ci & 3)) << 1) + (ci >> 2));
        cp_async4(ws_s + pos * 4, src, 4);
    }
    // patch: 32 lanes per row, incremental (ci, py) bookkeeping, no divides
    const int lane32 = tid & 31;
    int py = tid >> 5;              // starting row 0..7 (advance by 8)
    int ci = 0;
    const int gx = bx * 32 - 1 + lane32;
    const bool okx = ((unsigned)gx < 128u);
    const bool okx2 = ((unsigned)(gx + 32) < 128u) && (lane32 < 2);
#pragma unroll 4
    for (int r = tid >> 5; r < CB * 34; r += 8) {
        int gy = by * 32 + py - 1;
        bool oky = ((unsigned)gy < 128u);
        const float* srow = ib + (size_t)(c0 + ci) * NPIX + gy * IMGD;
        uint32_t drow = patch_s + (uint32_t)((ci * PCH + py * PROW) * 4);
        bool ok = oky && okx;
        cp_async4(drow + lane32 * 4, srow + (ok ? gx : 0), ok ? 4 : 0);
        if (lane32 < 2) {
            bool ok2 = oky && okx2;
            cp_async4(drow + (32 + lane32) * 4, srow + (ok2 ? (gx + 32) : 0), ok2 ? 4 : 0);
        }
        py += 8;
        if (py >= 34) { py -= 34; ci++; }
    }
}

// ---------------------------------------------------------------------------
// tf32 tensor-core 3x3 SAME conv + bias + relu.  Dual-camera (img<40 -> cam0).
// Block: 32x32 pixel tile x 16 ko, 256 threads (8 warps).
// Warp: 8-row band x 16 x-pixels x 16 ko; A reused across ky (sb+ky=row).
// ---------------------------------------------------------------------------
template<int CIN>
__global__ void __launch_bounds__(256, 2) conv3x3_tf32_kernel(
    const float* __restrict__ in,
    const float* __restrict__ wt0, const float* __restrict__ wt1,
    const float* __restrict__ bias0, const float* __restrict__ bias1,
    float* __restrict__ out, int groups)
{
    constexpr int CB = 8;
    constexpr int NCHUNK = CIN / CB;

    extern __shared__ __align__(16) float smem[];
    float* ws_base = smem;                         // 2 * WS_FLOATS
    float* patch_base = smem + 2 * WS_FLOATS;      // 2 * PATCH_FLOATS
    uint32_t sbase = (uint32_t)__cvta_generic_to_shared(smem);
    const uint32_t ws_off[2] = { sbase, sbase + (uint32_t)(WS_FLOATS * 4) };
    const uint32_t pa_off[2] = { sbase + (uint32_t)(2 * WS_FLOATS * 4),
                                 sbase + (uint32_t)((2 * WS_FLOATS + PATCH_FLOATS) * 4) };

    const int img = blockIdx.z / groups;
    const int grp = blockIdx.z % groups;
    const float* wt   = (img < NIMG_CAM) ? wt0 : wt1;
    const float* bias = (img < NIMG_CAM) ? bias0 : bias1;

    const int tid = threadIdx.x;
    const int w    = tid >> 5;
    const int lane = tid & 31;
    const int lg   = lane >> 2;         // 0..7
    const int tig  = lane & 3;          // 0..3
    const int wy   = w >> 1;            // band 0..3
    const int x0   = (w & 1) * 16;
    const int bx = (int)blockIdx.x;
    const int by = (int)blockIdx.y;

    const float* ib = in + (size_t)img * CIN * NPIX;

    float d[8][2][4];
#pragma unroll
    for (int sb = 0; sb < 8; sb++)
#pragma unroll
        for (int h = 0; h < 2; h++)
#pragma unroll
            for (int i = 0; i < 4; i++) d[sb][h][i] = 0.f;

    stage_chunk_tf32<CIN>(ib, wt, grp, bx, by, 0, ws_off[0], pa_off[0], tid);
    cp_commit();
    if (NCHUNK > 1) {
        stage_chunk_tf32<CIN>(ib, wt, grp, bx, by, CB, ws_off[1], pa_off[1], tid);
        cp_commit();
    }

    for (int ch = 0; ch < NCHUNK; ch++) {
        const int cur = ch & 1;
        if (ch + 1 < NCHUNK) cp_wait<1>(); else cp_wait<0>();
        __syncthreads();

        // B pointer in float2 units: element (k, ko, tig-pair)
        const float2* WB = (const float2*)(ws_base + cur * WS_FLOATS) + tig;
        const float* PA = patch_base + cur * PATCH_FLOATS
                        + tig * PCH + (wy * 8) * PROW + x0 + lg;

#pragma unroll
        for (int kx = 0; kx < 3; kx++) {
            float a[10][4];
#pragma unroll
            for (int r = 0; r < 10; r++) {
                const float* ap = PA + r * PROW + kx;
                a[r][0] = ap[0];
                a[r][1] = ap[8];
                a[r][2] = ap[4 * PCH];
                a[r][3] = ap[4 * PCH + 8];
            }
#pragma unroll
            for (int ky = 0; ky < 3; ky++) {
                const int k = ky * 3 + kx;
                float2 B0 = WB[(k * 16 + lg) * 4];       // ko = lg,     (ci tig, tig+4)
                float2 B1 = WB[(k * 16 + 8 + lg) * 4];   // ko = lg + 8
                float b0[2] = { B0.x, B0.y };
                float b1[2] = { B1.x, B1.y };
#pragma unroll
                for (int sb = 0; sb < 8; sb++) {
                    mma_tf32(d[sb][0], a[sb + ky], b0);
                    mma_tf32(d[sb][1], a[sb + ky], b1);
                }
            }
        }

        if (ch + 2 < NCHUNK) {
            __syncthreads();
            stage_chunk_tf32<CIN>(ib, wt, grp, bx, by, (ch + 2) * CB,
                                  ws_off[cur], pa_off[cur], tid);
            cp_commit();
        }
    }

    // epilogue: bias + relu + scalar stores
    float* ob = out + ((size_t)img * (groups * 16) + grp * 16) * NPIX;
    const int gxa = bx * 32 + x0 + lg;
    const int gxb = gxa + 8;
#pragma unroll
    for (int h = 0; h < 2; h++) {
        const int ko0 = h * 8 + 2 * tig;
        const float bi0 = bias[grp * 16 + ko0];
        const float bi1 = bias[grp * 16 + ko0 + 1];
        float* o0 = ob + (size_t)ko0 * NPIX;
        float* o1 = ob + (size_t)(ko0 + 1) * NPIX;
#pragma unroll
        for (int sb = 0; sb < 8; sb++) {
            const int gy = by * 32 + wy * 8 + sb;
            o0[gy * IMGD + gxa] = fmaxf(d[sb][h][0] + bi0, 0.f);
            o1[gy * IMGD + gxa] = fmaxf(d[sb][h][1] + bi1, 0.f);
            o0[gy * IMGD + gxb] = fmaxf(d[sb][h][2] + bi0, 0.f);
            o1[gy * IMGD + gxb] = fmaxf(d[sb][h][3] + bi1, 0.f);
        }
    }
}

// ---------------------------------------------------------------------------
// Layer-1 fp32 conv staging (scalar layout, CIN=3)
// ---------------------------------------------------------------------------
__device__ __forceinline__ void stage_l1(
    const float* __restrict__ ib, const float* __restrict__ wt,
    int g, int bx, int by, uint32_t ws_s, uint32_t patch_s, int tid)
{
    for (int idx = tid; idx < 3 * 144; idx += 256) {
        int ci = idx / 144;
        int rem = idx - ci * 144;
        int k = rem >> 4;
        int ko = rem & 15;
        const float* src = wt + ((size_t)(g * 16 + ko) * 3 + ci) * 9 + k;
        cp_async4(ws_s + idx * 4, src, 4);
    }
    const int lane32 = tid & 31;
    int py = tid >> 5;
    int ci = 0;
    const int gx = bx * 32 - 1 + lane32;
    const bool okx = ((unsigned)gx < 128u);
    for (int r = tid >> 5; r < 3 * 34; r += 8) {
        int gy = by * 32 + py - 1;
        bool oky = ((unsigned)gy < 128u);
        const float* srow = ib + (size_t)ci * NPIX + gy * IMGD;
        uint32_t drow = patch_s + (uint32_t)((ci * PCH + py * PROW) * 4);
        bool ok = oky && okx;
        cp_async4(drow + lane32 * 4, srow + (ok ? gx : 0), ok ? 4 : 0);
        if (lane32 < 2) {
            bool ok2 = oky && ((unsigned)(gx + 32) < 128u);
            cp_async4(drow + (32 + lane32) * 4, srow + (ok2 ? (gx + 32) : 0), ok2 ? 4 : 0);
        }
        py += 8;
        if (py >= 34) { py -= 34; ci++; }
    }
}

// ---------------------------------------------------------------------------
// Layer-1 fp32 conv (CIN=3), dual-camera.
// ---------------------------------------------------------------------------
__global__ void __launch_bounds__(256, 2) conv3x3_l1_kernel(
    const float* __restrict__ in0, const float* __restrict__ in1,
    const float* __restrict__ wt0, const float* __restrict__ wt1,
    const float* __restrict__ bias0, const float* __restrict__ bias1,
    float* __restrict__ out, int groups)
{
    extern __shared__ __align__(16) float smem[];
    float* ws_base = smem;
    float* patch_base = smem + 3 * 144;
    uint32_t sbase = (uint32_t)__cvta_generic_to_shared(smem);
    const uint32_t ws_s = sbase;
    const uint32_t pa_s = sbase + (uint32_t)(3 * 144 * 4);

    const int img = blockIdx.z / groups;
    const int g   = blockIdx.z % groups;
    const float* wt   = (img < NIMG_CAM) ? wt0 : wt1;
    const float* bias = (img < NIMG_CAM) ? bias0 : bias1;
    const int limg = (img < NIMG_CAM) ? img : (img - NIMG_CAM);
    const float* ib = ((img < NIMG_CAM) ? in0 : in1) + (size_t)limg * 3 * NPIX;

    const int tid = threadIdx.x;
    const int tx  = tid & 15;
    const int ty  = tid >> 4;
    const int bx  = (int)blockIdx.x;
    const int by  = (int)blockIdx.y;
    const int ox0 = bx * 32 + 2 * tx;
    const int oy0 = by * 32 + 2 * ty;

    unsigned long long acc[4][8];
    const unsigned long long z2 = pack2(0.f, 0.f);
#pragma unroll
    for (int p_ = 0; p_ < 4; p_++)
#pragma unroll
        for (int i = 0; i < 8; i++) acc[p_][i] = z2;

    stage_l1(ib, wt, g, bx, by, ws_s, pa_s, tid);
    cp_commit();
    cp_wait<0>();
    __syncthreads();

#pragma unroll
    for (int ci = 0; ci < 3; ci++) {
        float p[4][4];
        const float* pb = patch_base + ci * PCH + (2 * ty) * PROW + 2 * tx;
#pragma unroll
        for (int r = 0; r < 4; r++) {
            float2 a = *(const float2*)(pb + r * PROW);
            float2 b = *(const float2*)(pb + r * PROW + 2);
            p[r][0] = a.x; p[r][1] = a.y; p[r][2] = b.x; p[r][3] = b.y;
        }
        const float* wk = ws_base + ci * 144;
#pragma unroll
        for (int k = 0; k < 9; k++) {
            const int ky = k / 3, kx = k - 3 * (k / 3);
            const ulonglong2* wp = (const ulonglong2*)(wk + k * 16);
            ulonglong2 w01 = wp[0];
            ulonglong2 w23 = wp[1];
            ulonglong2 w45 = wp[2];
            ulonglong2 w67 = wp[3];
#pragma unroll
            for (int p_ = 0; p_ < 4; p_++) {
                float v = p[(p_ >> 1) + ky][(p_ & 1) + kx];
                unsigned long long bb = pack2(v, v);
                fma2(acc[p_][0], w01.x, bb);
                fma2(acc[p_][1], w01.y, bb);
                fma2(acc[p_][2], w23.x, bb);
                fma2(acc[p_][3], w23.y, bb);
                fma2(acc[p_][4], w45.x, bb);
                fma2(acc[p_][5], w45.y, bb);
                fma2(acc[p_][6], w67.x, bb);
                fma2(acc[p_][7], w67.y, bb);
            }
        }
    }

    float* ob = out + ((size_t)img * (groups * 16) + g * 16) * NPIX;
#pragma unroll
    for (int i = 0; i < 8; i++) {
        float b0 = bias[g * 16 + 2 * i];
        float b1 = bias[g * 16 + 2 * i + 1];
#pragma unroll
        for (int pr = 0; pr < 2; pr++) {
            float a0l, a1l, a0r, a1r;
            unpack2(acc[pr * 2 + 0][i], a0l, a1l);
            unpack2(acc[pr * 2 + 1][i], a0r, a1r);
            int row = oy0 + pr;
            float2 v0 = make_float2(fmaxf(a0l + b0, 0.f), fmaxf(a0r + b0, 0.f));
            float2 v1 = make_float2(fmaxf(a1l + b1, 0.f), fmaxf(a1r + b1, 0.f));
            *(float2*)(ob + (size_t)(2 * i) * NPIX + row * IMGD + ox0) = v0;
            *(float2*)(ob + (size_t)(2 * i + 1) * NPIX + row * IMGD + ox0) = v1;
        }
    }
}

// ---------------------------------------------------------------------------
// Spatial softmax (conv16 laid out img-major: ((img*16)+ch)*NPIX)
// ---------------------------------------------------------------------------
__global__ void __launch_bounds__(256) sspmax_kernel(
    const float* __restrict__ conv16, float* __restrict__ feat)
{
    __shared__ float red[8];
    __shared__ float r2[3][8];

    const int id = blockIdx.x;
    const int img = id >> 4;
    const int ch = id & 15;
    const int cam = (img >= NIMG_CAM) ? 1 : 0;
    const int bt = img - cam * NIMG_CAM;
    const float* p = conv16 + ((size_t)img * 16 + ch) * NPIX;
    const int tid = threadIdx.x;

    float m = -1e30f;
    for (int k = tid; k < NPIX; k += 256) m = fmaxf(m, p[k]);
    for (int o = 16; o; o >>= 1) m = fmaxf(m, __shfl_xor_sync(~0u, m, o));
    if ((tid & 31) == 0) red[tid >> 5] = m;
    __syncthreads();
    if (tid < 8) {
        float v = red[tid];
        for (int o = 4; o; o >>= 1) v = fmaxf(v, __shfl_xor_sync(0xffu, v, o));
        if (tid == 0) red[0] = v;
    }
    __syncthreads();
    m = red[0];

    float se = 0.f, sx = 0.f, sy = 0.f;
    const float step = 2.f / 127.f;
    for (int k = tid; k < NPIX; k += 256) {
        float e = expf(p[k] - m);
        float px = -1.f + (float)(k & 127) * step;
        float py = -1.f + (float)(k >> 7) * step;
        se += e; sx += e * px; sy += e * py;
    }
    for (int o = 16; o; o >>= 1) {
        se += __shfl_xor_sync(~0u, se, o);
        sx += __shfl_xor_sync(~0u, sx, o);
        sy += __shfl_xor_sync(~0u, sy, o);
    }
    if ((tid & 31) == 0) { r2[0][tid >> 5] = se; r2[1][tid >> 5] = sx; r2[2][tid >> 5] = sy; }
    __syncthreads();
    if (tid == 0) {
        float a = 0.f, bx = 0.f, by = 0.f;
        for (int w = 0; w < 8; w++) { a += r2[0][w]; bx += r2[1][w]; by += r2[2][w]; }
        feat[bt * 64 + cam * 32 + 2 * ch + 0] = bx / a;
        feat[bt * 64 + cam * 32 + 2 * ch + 1] = by / a;
    }
}

// ---------------------------------------------------------------------------
// LSTM cell
// ---------------------------------------------------------------------------
__device__ __forceinline__ float sigm(float x) { return 1.f / (1.f + expf(-x)); }

__global__ void __launch_bounds__(256) lstm_cell_kernel(
    const float* __restrict__ xa, int alen, int xa_stride,
    const float* __restrict__ im,
    const float* __restrict__ wih, const float* __restrict__ whh,
    const float* __restrict__ bih, const float* __restrict__ bhh,
    const float* __restrict__ hprev, float* __restrict__ hnew,
    float* __restrict__ c)
{
    __shared__ float xs[BB][576];
    __shared__ float hs[BB][HID];
    __shared__ float part[8][BB];
    __shared__ float gs[16];

    const int inlen = alen + 64;
    const int tid = threadIdx.x;

    for (int idx = tid; idx < BB * inlen; idx += 256) {
        int b = idx / inlen;
        int k = idx - b * inlen;
        xs[b][k] = (k < alen) ? xa[b * xa_stride + k] : im[b * (TT * 64) + (k - alen)];
    }
    for (int idx = tid; idx < BB * HID; idx += 256)
        hs[idx >> 9][idx & 511] = hprev[idx];
    __syncthreads();

    const int j = blockIdx.x;
    const int warp = tid >> 5;
    const int lane = tid & 31;
    const int g = warp >> 1;
    const int half = warp & 1;
    const int row = g * HID + j;
    const int k0 = half * 32 + lane;

    float s0 = 0.f, s1 = 0.f, s2 = 0.f, s3 = 0.f;
    const float* wr = wih + (size_t)row * inlen;
#pragma unroll 4
    for (int k = k0; k < inlen; k += 64) {
        float w = wr[k];
        s0 += w * xs[0][k]; s1 += w * xs[1][k];
        s2 += w * xs[2][k]; s3 += w * xs[3][k];
    }
    const float* hr = whh + (size_t)row * HID;
#pragma unroll 4
    for (int k = k0; k < HID; k += 64) {
        float w = hr[k];
        s0 += w * hs[0][k]; s1 += w * hs[1][k];
        s2 += w * hs[2][k]; s3 += w * hs[3][k];
    }
    for (int o = 16; o; o >>= 1) {
        s0 += __shfl_xor_sync(~0u, s0, o);
        s1 += __shfl_xor_sync(~0u, s1, o);
        s2 += __shfl_xor_sync(~0u, s2, o);
        s3 += __shfl_xor_sync(~0u, s3, o);
    }
    if (lane == 0) {
        part[warp][0] = s0; part[warp][1] = s1;
        part[warp][2] = s2; part[warp][3] = s3;
    }
    __syncthreads();

    if (tid < 16) {
        int gg = tid >> 2, b = tid & 3;
        float s = part[gg * 2][b] + part[gg * 2 + 1][b]
                + bih[gg * HID + j] + bhh[gg * HID + j];
        gs[b * 4 + gg] = s;
    }
    __syncthreads();

    if (tid < BB) {
        const int b = tid;
        float gi = gs[b * 4 + 0];
        float gf = gs[b * 4 + 1];
        float gg = gs[b * 4 + 2];
        float go = gs[b * 4 + 3];
        float cold = c[b * HID + j];
        float cn = sigm(gf) * cold + sigm(gi) * tanhf(gg);
        float hn = sigm(go) * tanhf(cn);
        c[b * HID + j] = cn;
        hnew[b * HID + j] = hn;
    }
}

// ---------------------------------------------------------------------------
// Output head
// ---------------------------------------------------------------------------
__global__ void __launch_bounds__(128) out_kernel(
    const float* __restrict__ h, const float* __restrict__ im,
    const float* __restrict__ ow, const float* __restrict__ ob,
    float* __restrict__ outp)
{
    const int b = blockIdx.x / AA;
    const int a = blockIdx.x % AA;
    const float* w = ow + a * (HID + 64);
    float s = 0.f;
    for (int k = threadIdx.x; k < HID; k += 128) s += w[k] * h[b * HID + k];
    for (int k = threadIdx.x; k < 64; k += 128) s += w[HID + k] * im[b * (TT * 64) + k];
    __shared__ float red[4];
    for (int o = 16; o; o >>= 1) s += __shfl_xor_sync(~0u, s, o);
    if ((threadIdx.x & 31) == 0) red[threadIdx.x >> 5] = s;
    __syncthreads();
    if (threadIdx.x == 0)
        outp[b * (TT * AA) + a] = red[0] + red[1] + red[2] + red[3] + ob[a];
}

__global__ void zero_state_kernel()
{
    int i = blockIdx.x * blockDim.x + threadIdx.x;
    if (i < 2 * LL * BB * HID) g_h[i] = 0.f;
    if (i < LL * BB * HID) g_c[i] = 0.f;
}

// ---------------------------------------------------------------------------
// Launch
// ---------------------------------------------------------------------------
extern "C" void kernel_launch(void* const* d_in, const int* in_sizes, int n_in,
                              void* d_out, int out_size)
{
    (void)in_sizes; (void)n_in; (void)out_size;

    const float* img_m  = (const float*)d_in[0];
    const float* img_s  = (const float*)d_in[1];
    const float* states = (const float*)d_in[2];
    const float* wih0 = (const float*)d_in[19];
    const float* whh0 = (const float*)d_in[20];
    const float* bih0 = (const float*)d_in[21];
    const float* bhh0 = (const float*)d_in[22];
    const float* wih_r = (const float*)d_in[23];
    const float* whh_r = (const float*)d_in[24];
    const float* bih_r = (const float*)d_in[25];
    const float* bhh_r = (const float*)d_in[26];
    const float* out_w = (const float*)d_in[27];
    const float* out_b = (const float*)d_in[28];
    float* outp = (float*)d_out;

    float* bufA; cudaGetSymbolAddress((void**)&bufA, g_bufA);
    float* bufB; cudaGetSymbolAddress((void**)&bufB, g_bufB);
    float* feat; cudaGetSymbolAddress((void**)&feat, g_feat);
    float* hbuf; cudaGetSymbolAddress((void**)&hbuf, g_h);
    float* cbuf; cudaGetSymbolAddress((void**)&cbuf, g_c);

    const int smemL1 = (3 * 144 + 3 * PCH) * 4;                 // 16416
    const int smemTF = 2 * (WS_FLOATS + PATCH_FLOATS) * 4;      // 87552
    cudaFuncSetAttribute(conv3x3_l1_kernel,        cudaFuncAttributeMaxDynamicSharedMemorySize, smemL1);
    cudaFuncSetAttribute(conv3x3_tf32_kernel<32>,  cudaFuncAttributeMaxDynamicSharedMemorySize, smemTF);
    cudaFuncSetAttribute(conv3x3_tf32_kernel<64>,  cudaFuncAttributeMaxDynamicSharedMemorySize, smemTF);
    cudaFuncSetAttribute(conv3x3_tf32_kernel<128>, cudaFuncAttributeMaxDynamicSharedMemorySize, smemTF);

    zero_state_kernel<<<96, 256>>>();

    const float* mw[4] = { (const float*)d_in[3], (const float*)d_in[5],
                           (const float*)d_in[7], (const float*)d_in[9] };
    const float* mb[4] = { (const float*)d_in[4], (const float*)d_in[6],
                           (const float*)d_in[8], (const float*)d_in[10] };
    const float* sw[4] = { (const float*)d_in[11], (const float*)d_in[13],
                           (const float*)d_in[15], (const float*)d_in[17] };
    const float* sb[4] = { (const float*)d_in[12], (const float*)d_in[14],
                           (const float*)d_in[16], (const float*)d_in[18] };

    // Buffer plan (img-major everywhere):
    //  L1 -> a32  (bufA), L2 reads a32 -> b64 (bufB),
    //  L3 reads b64 -> a128 (bufA, a32 dead), L4 reads a128 -> b16 (bufB, b64 dead)
    float* a32  = bufA;
    float* b64  = bufB;
    float* a128 = bufA;
    float* b16  = bufB;

    conv3x3_l1_kernel<<<dim3(4, 4, NIMG * 2), 256, smemL1>>>(
        img_m, img_s, mw[0], sw[0], mb[0], sb[0], a32, 2);
    conv3x3_tf32_kernel<32><<<dim3(4, 4, NIMG * 4), 256, smemTF>>>(
        a32, mw[1], sw[1], mb[1], sb[1], b64, 4);
    conv3x3_tf32_kernel<64><<<dim3(4, 4, NIMG * 8), 256, smemTF>>>(
        b64, mw[2], sw[2], mb[2], sb[2], a128, 8);
    conv3x3_tf32_kernel<128><<<dim3(4, 4, NIMG * 1), 256, smemTF>>>(
        a128, mw[3], sw[3], mb[3], sb[3], b16, 1);

    sspmax_kernel<<<NIMG * 16, 256>>>(b16, feat);

    const int half = LL * BB * HID;
    for (int t = 0; t < TT; t++) {
        float* hprev = hbuf + (t & 1) * half;
        float* hcur  = hbuf + (1 - (t & 1)) * half;
        const float* im_t = feat + t * 64;

        lstm_cell_kernel<<<HID, 256>>>(
            states + t * SS, SS, TT * SS, im_t,
            wih0, whh0, bih0, bhh0,
            hprev + 0, hcur + 0, cbuf + 0);

        for (int l = 1; l < LL; l++) {
            lstm_cell_kernel<<<HID, 256>>>(
                hcur + (size_t)(l - 1) * BB * HID, HID, HID, im_t,
                wih_r + (size_t)(l - 1) * 4 * HID * (HID + 64),
                whh_r + (size_t)(l - 1) * 4 * HID * HID,
                bih_r + (size_t)(l - 1) * 4 * HID,
                bhh_r + (size_t)(l - 1) * 4 * HID,
                hprev + (size_t)l * BB * HID,
                hcur + (size_t)l * BB * HID,
                cbuf + (size_t)l * BB * HID);
        }

        out_kernel<<<BB * AA, 128>>>(
            hcur + (size_t)(LL - 1) * BB * HID, im_t, out_w, out_b, outp + t * AA);
    }
}